// round 1
// baseline (speedup 1.0000x reference)
#include <cuda_runtime.h>
#include <cuda_bf16.h>
#include <cstdint>

// Problem constants
#define BATCH 4
#define CH    128
#define HW    64
#define PQ    4096            // HW*HW
#define SCALE 10.0f
#define EPS_SUM 0.1152f       // 128*3*3*1e-4

// ---------------- static scratch (no allocations allowed) ----------------
__device__ float g_G[(size_t)BATCH * PQ * PQ];   // Gt[b][p][q] = sum_c b[c,p]*f[c,q]  (256 MB)
__device__ float g_ssq[BATCH * PQ];              // per-pixel squared norm of b
__device__ float g_coef[BATCH * PQ];             // SCALE * mm[p] / denom[b,p]
__device__ float g_mm[PQ];                       // mask gate per p (1 = keep)
__device__ float g_partial[BATCH * 64 * PQ];     // per-p-block column exp partial sums
__device__ float g_colsum[BATCH * PQ];           // softmax denominators per (b,q)

// ---------------- K0a: ssq[b,p] = sum_c b[b,c,p]^2 ----------------
__global__ void k_ssq(const float* __restrict__ bin) {
    int p = blockIdx.x * 256 + threadIdx.x;
    int b = blockIdx.y;
    const float* src = bin + ((size_t)b * CH) * PQ + p;
    float s = 0.f;
#pragma unroll 8
    for (int c = 0; c < CH; c++) {
        float v = src[(size_t)c * PQ];
        s += v * v;
    }
    g_ssq[b * PQ + p] = s;
}

// ---------------- K0b: coef[b,p] = SCALE*mm[p]/sqrt(3x3 ssq sum + eps) ----------------
__global__ void k_prep(const float* __restrict__ mask) {
    int p = blockIdx.x * 256 + threadIdx.x;
    int b = blockIdx.y;
    int py = p >> 6, px = p & 63;

    float s = EPS_SUM;
    bool masked = false;
#pragma unroll
    for (int dy = -1; dy <= 1; dy++) {
#pragma unroll
        for (int dx = -1; dx <= 1; dx++) {
            int yy = py + dy, xx = px + dx;
            if ((unsigned)yy < 64u && (unsigned)xx < 64u) {
                s += g_ssq[b * PQ + (yy << 6) + xx];
                // mask_s = mask[0,0,::8,::8]; patch mean == 0 iff all in-bounds samples zero
                if (mask[(size_t)(yy * 8) * 512 + xx * 8] != 0.0f) masked = true;
            }
        }
    }
    g_coef[b * PQ + p] = masked ? 0.0f : (SCALE / sqrtf(s));
    if (b == 0) g_mm[p] = masked ? 0.0f : 1.0f;
}

// ---------------- K1: SGEMM  Gt[b][p][q] = sum_c b[c,p] * f[c,q] ----------------
// M = N = 4096, K = 128. Tile 128x128, BK=16, 256 threads, 8x8 microtile.
#define BM 128
#define BN 128
#define BKK 16
__global__ __launch_bounds__(256, 2) void k_gemm(const float* __restrict__ fin,
                                                 const float* __restrict__ bin) {
    int b  = blockIdx.z;
    int m0 = blockIdx.y * BM;     // p tile
    int n0 = blockIdx.x * BN;     // q tile
    const float* A  = bin + (size_t)b * CH * PQ;   // A[c][p]
    const float* Bf = fin + (size_t)b * CH * PQ;   // B[c][q]

    __shared__ __align__(16) float As[BKK][BM];
    __shared__ __align__(16) float Bs[BKK][BN];

    int t  = threadIdx.x;
    int tx = t & 15;
    int ty = t >> 4;

    float acc[8][8];
#pragma unroll
    for (int i = 0; i < 8; i++)
#pragma unroll
        for (int j = 0; j < 8; j++) acc[i][j] = 0.f;

#pragma unroll 1
    for (int k0 = 0; k0 < CH; k0 += BKK) {
        // 512 float4 per operand tile; each thread loads 2
#pragma unroll
        for (int i = 0; i < 2; i++) {
            int idx = t + i * 256;
            int row = idx >> 5;            // 0..15
            int c4  = (idx & 31) << 2;     // 0..124
            *(float4*)&As[row][c4] = *(const float4*)(A  + (size_t)(k0 + row) * PQ + m0 + c4);
            *(float4*)&Bs[row][c4] = *(const float4*)(Bf + (size_t)(k0 + row) * PQ + n0 + c4);
        }
        __syncthreads();

#pragma unroll
        for (int k = 0; k < BKK; k++) {
            float af[8], bf[8];
            *(float4*)&af[0] = *(const float4*)&As[k][ty * 8 + 0];
            *(float4*)&af[4] = *(const float4*)&As[k][ty * 8 + 4];
            *(float4*)&bf[0] = *(const float4*)&Bs[k][tx * 8 + 0];
            *(float4*)&bf[4] = *(const float4*)&Bs[k][tx * 8 + 4];
#pragma unroll
            for (int i = 0; i < 8; i++)
#pragma unroll
                for (int j = 0; j < 8; j++) acc[i][j] += af[i] * bf[j];
        }
        __syncthreads();
    }

    float* Gp = g_G + (size_t)b * PQ * PQ;
#pragma unroll
    for (int i = 0; i < 8; i++) {
        size_t row = (size_t)(m0 + ty * 8 + i) * PQ + n0 + tx * 8;
        *(float4*)&Gp[row + 0] = make_float4(acc[i][0], acc[i][1], acc[i][2], acc[i][3]);
        *(float4*)&Gp[row + 4] = make_float4(acc[i][4], acc[i][5], acc[i][6], acc[i][7]);
    }
}

// ---------------- K2: 9-point shifted sum + exp + out + column partials ----------------
// block: 256 threads -> q chunk of 128 (2 p-lanes), p tile of 64.
#define PTILE 64
__global__ __launch_bounds__(256) void k_sum9(float* __restrict__ out) {
    int b    = blockIdx.z;
    int q0   = blockIdx.x * 128;
    int pblk = blockIdx.y;
    int p0   = pblk * PTILE;

    int t  = threadIdx.x;
    int tq = t & 127;
    int tp = t >> 7;                 // 0 or 1
    int q  = q0 + tq;
    int qy = q >> 6, qx = q & 63;

    const float* Gp   = g_G + (size_t)b * PQ * PQ;
    const float* coef = g_coef + b * PQ;
    float partial = 0.f;

    for (int p = p0 + tp; p < p0 + PTILE; p += 2) {
        int py = p >> 6, px = p & 63;
        float s = 0.f;
#pragma unroll
        for (int dy = -1; dy <= 1; dy++) {
#pragma unroll
            for (int dx = -1; dx <= 1; dx++) {
                bool ok = (unsigned)(qy + dy) < 64u && (unsigned)(qx + dx) < 64u &&
                          (unsigned)(py + dy) < 64u && (unsigned)(px + dx) < 64u;
                int d = dy * 64 + dx;
                if (ok) s += __ldg(&Gp[(size_t)(p + d) * PQ + (q + d)]);
            }
        }
        float e = __expf(s * coef[p]);
        out[((size_t)(b * PQ + p)) * PQ + q] = e;
        partial += e;
    }

    __shared__ float red[256];
    red[t] = partial;
    __syncthreads();
    if (tp == 0)
        g_partial[((size_t)(b * 64 + pblk)) * PQ + q] = red[tq] + red[128 + tq];
}

// ---------------- K2b: deterministic reduction of column partials ----------------
__global__ void k_colreduce() {
    int q = blockIdx.x * 256 + threadIdx.x;
    int b = blockIdx.y;
    const float* src = g_partial + (size_t)(b * 64) * PQ + q;
    float s = 0.f;
#pragma unroll 8
    for (int j = 0; j < 64; j++) s += src[(size_t)j * PQ];
    g_colsum[b * PQ + q] = s;
}

// ---------------- K3: normalize: out = mm[p] * exp / colsum[b,q] ----------------
__global__ void k_norm(float* __restrict__ out) {
    size_t i4  = (size_t)blockIdx.x * 256 + threadIdx.x;   // float4 index
    size_t row = i4 >> 10;                                  // PQ/4 = 1024 f4 per row
    int p = (int)(row & 4095);
    int b = (int)(row >> 12);
    int c4 = (int)(i4 & 1023);

    float4 v  = ((float4*)out)[i4];
    float  m  = g_mm[p];
    float4 cs = ((const float4*)g_colsum)[b * 1024 + c4];
    v.x = m * v.x / cs.x;
    v.y = m * v.y / cs.y;
    v.z = m * v.z / cs.z;
    v.w = m * v.w / cs.w;
    ((float4*)out)[i4] = v;
}

// ---------------- launch ----------------
extern "C" void kernel_launch(void* const* d_in, const int* in_sizes, int n_in,
                              void* d_out, int out_size) {
    const float* f    = (const float*)d_in[0];
    const float* bb   = (const float*)d_in[1];
    const float* mask = (const float*)d_in[2];
    float* out = (float*)d_out;

    k_ssq      <<<dim3(PQ / 256, BATCH), 256>>>(bb);
    k_prep     <<<dim3(PQ / 256, BATCH), 256>>>(mask);
    k_gemm     <<<dim3(PQ / BN, PQ / BM, BATCH), 256>>>(f, bb);
    k_sum9     <<<dim3(PQ / 128, PQ / PTILE, BATCH), 256>>>(out);
    k_colreduce<<<dim3(PQ / 256, BATCH), 256>>>();
    k_norm     <<<(unsigned)(((size_t)BATCH * PQ * PQ / 4) / 256), 256>>>(out);
}

// round 4
// speedup vs baseline: 1.1954x; 1.1954x over previous
#include <cuda_runtime.h>
#include <cuda_bf16.h>
#include <cstdint>

// Problem constants
#define BATCH 4
#define CH    128
#define HW    64
#define PQ    4096            // HW*HW
#define SCALE 10.0f
#define EPS_SUM 0.1152f       // 128*3*3*1e-4
#define LOG2E 1.4426950408889634f

// ---------------- static scratch (no allocations allowed) ----------------
__device__ float g_G[(size_t)BATCH * PQ * PQ];   // Gt[b][p][q] = sum_c b[c,p]*f[c,q]  (256 MB)
__device__ float g_ssq[BATCH * PQ];              // per-pixel squared norm of b
__device__ float g_coef[BATCH * PQ];             // SCALE*log2e*mm[p]/denom[b,p]
__device__ float g_mm[PQ];                       // mask gate per p (1 = keep)
__device__ float g_partial[BATCH * 64 * PQ];     // per-p-row column exp partial sums
__device__ float g_colsum[BATCH * PQ];           // softmax denominators per (b,q)

// fast 2^t on the FMA pipe (degree-5 Taylor on [-0.5,0.5], rel err ~2.4e-6)
__device__ __forceinline__ float fast_exp2(float t) {
    t = fminf(fmaxf(t, -120.0f), 120.0f);
    float fn = rintf(t);
    float f  = t - fn;
    float p  = 1.3333558e-3f;
    p = fmaf(p, f, 9.6181291e-3f);
    p = fmaf(p, f, 5.5504109e-2f);
    p = fmaf(p, f, 2.4022651e-1f);
    p = fmaf(p, f, 6.9314718e-1f);
    p = fmaf(p, f, 1.0f);
    int n = (int)fn;
    return p * __int_as_float((n + 127) << 23);
}

// ---------------- K0a: ssq[b,p] = sum_c b[b,c,p]^2 ----------------
__global__ void k_ssq(const float* __restrict__ bin) {
    int p = blockIdx.x * 256 + threadIdx.x;
    int b = blockIdx.y;
    const float* src = bin + ((size_t)b * CH) * PQ + p;
    float s = 0.f;
#pragma unroll 8
    for (int c = 0; c < CH; c++) {
        float v = src[(size_t)c * PQ];
        s += v * v;
    }
    g_ssq[b * PQ + p] = s;
}

// ---------------- K0b: coef[b,p] = SCALE*log2e*mm[p]/sqrt(3x3 ssq sum + eps) --------
__global__ void k_prep(const float* __restrict__ mask) {
    int p = blockIdx.x * 256 + threadIdx.x;
    int b = blockIdx.y;
    int py = p >> 6, px = p & 63;

    float s = EPS_SUM;
    bool masked = false;
#pragma unroll
    for (int dy = -1; dy <= 1; dy++) {
#pragma unroll
        for (int dx = -1; dx <= 1; dx++) {
            int yy = py + dy, xx = px + dx;
            if ((unsigned)yy < 64u && (unsigned)xx < 64u) {
                s += g_ssq[b * PQ + (yy << 6) + xx];
                if (mask[(size_t)(yy * 8) * 512 + xx * 8] != 0.0f) masked = true;
            }
        }
    }
    g_coef[b * PQ + p] = masked ? 0.0f : (SCALE * LOG2E / sqrtf(s));
    if (b == 0) g_mm[p] = masked ? 0.0f : 1.0f;
}

// ---------------- K1: SGEMM  Gt[b][p][q] = sum_c b[c,p] * f[c,q] ----------------
#define BM 128
#define BN 128
#define BKK 16
__global__ __launch_bounds__(256, 2) void k_gemm(const float* __restrict__ fin,
                                                 const float* __restrict__ bin) {
    int b  = blockIdx.z;
    int m0 = blockIdx.y * BM;     // p tile
    int n0 = blockIdx.x * BN;     // q tile
    const float* A  = bin + (size_t)b * CH * PQ;   // A[c][p]
    const float* Bf = fin + (size_t)b * CH * PQ;   // B[c][q]

    __shared__ __align__(16) float As[BKK][BM];
    __shared__ __align__(16) float Bs[BKK][BN];

    int t  = threadIdx.x;
    int tx = t & 15;
    int ty = t >> 4;

    float acc[8][8];
#pragma unroll
    for (int i = 0; i < 8; i++)
#pragma unroll
        for (int j = 0; j < 8; j++) acc[i][j] = 0.f;

#pragma unroll 1
    for (int k0 = 0; k0 < CH; k0 += BKK) {
#pragma unroll
        for (int i = 0; i < 2; i++) {
            int idx = t + i * 256;
            int row = idx >> 5;
            int c4  = (idx & 31) << 2;
            *(float4*)&As[row][c4] = *(const float4*)(A  + (size_t)(k0 + row) * PQ + m0 + c4);
            *(float4*)&Bs[row][c4] = *(const float4*)(Bf + (size_t)(k0 + row) * PQ + n0 + c4);
        }
        __syncthreads();

#pragma unroll
        for (int k = 0; k < BKK; k++) {
            float af[8], bf[8];
            *(float4*)&af[0] = *(const float4*)&As[k][ty * 8 + 0];
            *(float4*)&af[4] = *(const float4*)&As[k][ty * 8 + 4];
            *(float4*)&bf[0] = *(const float4*)&Bs[k][tx * 8 + 0];
            *(float4*)&bf[4] = *(const float4*)&Bs[k][tx * 8 + 4];
#pragma unroll
            for (int i = 0; i < 8; i++)
#pragma unroll
                for (int j = 0; j < 8; j++) acc[i][j] += af[i] * bf[j];
        }
        __syncthreads();
    }

    float* Gp = g_G + (size_t)b * PQ * PQ;
#pragma unroll
    for (int i = 0; i < 8; i++) {
        size_t row = (size_t)(m0 + ty * 8 + i) * PQ + n0 + tx * 8;
        *(float4*)&Gp[row + 0] = make_float4(acc[i][0], acc[i][1], acc[i][2], acc[i][3]);
        *(float4*)&Gp[row + 4] = make_float4(acc[i][4], acc[i][5], acc[i][6], acc[i][7]);
    }
}

// ---------------- K2: 9-tap diagonal sum + exp2 + out + column partials ----------------
// One block = one p-row (64 p) x 256 q. All 9 tap addresses are base + d*4097
// (compile-time constant element offsets); base advances by PQ per px step.
__global__ __launch_bounds__(256) void k_sum9(float* __restrict__ out) {
    int b    = blockIdx.z;
    int prow = blockIdx.y;                 // py, constant per block
    int q    = blockIdx.x * 256 + threadIdx.x;
    int qy   = q >> 6, qx = q & 63;

    const float* __restrict__ Gp = g_G + (size_t)b * PQ * PQ;
    const float* __restrict__ cf = g_coef + b * PQ + prow * 64;

    // loop-invariant row validity (dy = -1, +1); dy = 0 always valid
    const bool rvm = (prow > 0)  && (qy > 0);
    const bool rvp = (prow < 63) && (qy < 63);
    const bool qlf = (qx > 0), qrt = (qx < 63);

    const float* base = Gp + (size_t)(prow * 64) * PQ + q;
    float* orow = out + ((size_t)(b * PQ + prow * 64)) * PQ + q;
    float partial = 0.f;

#pragma unroll 4
    for (int px = 0; px < 64; px++) {
        bool lf = qlf && (px > 0);
        bool rt = qrt && (px < 63);
        float s = 0.f;
        if (rvm) {
            if (lf) s += __ldg(base - 65 * 4097);
            s += __ldg(base - 64 * 4097);
            if (rt) s += __ldg(base - 63 * 4097);
        }
        if (lf) s += __ldg(base - 4097);
        s += __ldg(base);
        if (rt) s += __ldg(base + 4097);
        if (rvp) {
            if (lf) s += __ldg(base + 63 * 4097);
            s += __ldg(base + 64 * 4097);
            if (rt) s += __ldg(base + 65 * 4097);
        }
        float e = fast_exp2(s * cf[px]);
        *orow = e;
        partial += e;
        base += PQ;
        orow += PQ;
    }
    g_partial[((size_t)(b * 64 + prow)) * PQ + q] = partial;
}

// ---------------- K2b: deterministic reduction of column partials ----------------
__global__ void k_colreduce() {
    int q = blockIdx.x * 256 + threadIdx.x;
    int b = blockIdx.y;
    const float* src = g_partial + (size_t)(b * 64) * PQ + q;
    float s = 0.f;
#pragma unroll 8
    for (int j = 0; j < 64; j++) s += src[(size_t)j * PQ];
    g_colsum[b * PQ + q] = s;
}

// ---------------- K3: normalize: out = mm[p] * exp / colsum[b,q] ----------------
__global__ void k_norm(float* __restrict__ out) {
    size_t i4  = (size_t)blockIdx.x * 256 + threadIdx.x;
    size_t row = i4 >> 10;                  // 1024 float4 per row
    int p  = (int)(row & 4095);
    int b  = (int)(row >> 12);
    int c4 = (int)(i4 & 1023);

    float4 v  = ((float4*)out)[i4];
    float  m  = g_mm[p];
    float4 cs = ((const float4*)g_colsum)[b * 1024 + c4];
    v.x = m * v.x / cs.x;
    v.y = m * v.y / cs.y;
    v.z = m * v.z / cs.z;
    v.w = m * v.w / cs.w;
    ((float4*)out)[i4] = v;
}

// ---------------- launch ----------------
extern "C" void kernel_launch(void* const* d_in, const int* in_sizes, int n_in,
                              void* d_out, int out_size) {
    const float* f    = (const float*)d_in[0];
    const float* bb   = (const float*)d_in[1];
    const float* mask = (const float*)d_in[2];
    float* out = (float*)d_out;

    k_ssq      <<<dim3(PQ / 256, BATCH), 256>>>(bb);
    k_prep     <<<dim3(PQ / 256, BATCH), 256>>>(mask);
    k_gemm     <<<dim3(PQ / BN, PQ / BM, BATCH), 256>>>(f, bb);
    k_sum9     <<<dim3(PQ / 256, 64, BATCH), 256>>>(out);
    k_colreduce<<<dim3(PQ / 256, BATCH), 256>>>();
    k_norm     <<<(unsigned)(((size_t)BATCH * PQ * PQ / 4) / 256), 256>>>(out);
}

// round 9
// speedup vs baseline: 1.5619x; 1.3066x over previous
#include <cuda_runtime.h>
#include <cuda_bf16.h>
#include <cstdint>

// Problem constants
#define BATCH 4
#define CH    128
#define HW    64
#define PQ    4096            // HW*HW
#define SCALE 10.0f
#define EPS_SUM 0.1152f       // 128*3*3*1e-4
#define LOG2E 1.4426950408889634f
#define KTOT  384             // split-bf16 packed K (ah|al|ah vs bh|bh|bl)
#define BKP   32              // bf16 K per pipeline stage
#define NKIT  (KTOT / BKP)    // 12 stages
#define LDT   40              // padded smem row length (bf16)

// ---------------- static scratch ----------------
__device__ float g_G[(size_t)BATCH * PQ * PQ];   // Gt[b][p][q]  (256 MB)
__device__ float g_ssq[BATCH * PQ];
__device__ float g_coef[BATCH * PQ];
__device__ float g_mm[PQ];
__device__ float g_partial[BATCH * 64 * PQ];
__device__ float g_colsum[BATCH * PQ];
__device__ __nv_bfloat16 g_Apack[(size_t)BATCH * PQ * KTOT];  // from b: [p][ah|al|ah]
__device__ __nv_bfloat16 g_Bpack[(size_t)BATCH * PQ * KTOT];  // from f: [q][bh|bh|bl]

// ---------------- helpers ----------------
__device__ __forceinline__ uint32_t smem_u32(const void* p) {
    uint32_t a;
    asm("{ .reg .u64 t; cvta.to.shared.u64 t, %1; cvt.u32.u64 %0, t; }" : "=r"(a) : "l"(p));
    return a;
}
__device__ __forceinline__ void cpa16(void* dst, const void* src) {
    asm volatile("cp.async.ca.shared.global [%0], [%1], 16;"
                 :: "r"(smem_u32(dst)), "l"(src));
}
#define CP_COMMIT() asm volatile("cp.async.commit_group;" ::: "memory")
#define CP_WAIT(n)  asm volatile("cp.async.wait_group %0;" :: "n"(n) : "memory")

__device__ __forceinline__ void mma16816(float* c, const uint32_t* a, const uint32_t* bfr) {
    asm volatile(
        "mma.sync.aligned.m16n8k16.row.col.f32.bf16.bf16.f32 "
        "{%0,%1,%2,%3}, {%4,%5,%6,%7}, {%8,%9}, {%0,%1,%2,%3};"
        : "+f"(c[0]), "+f"(c[1]), "+f"(c[2]), "+f"(c[3])
        : "r"(a[0]), "r"(a[1]), "r"(a[2]), "r"(a[3]), "r"(bfr[0]), "r"(bfr[1]));
}

// fast 2^t on the FMA pipe (degree-5, rel err ~2.4e-6)
__device__ __forceinline__ float fast_exp2(float t) {
    t = fminf(fmaxf(t, -120.0f), 120.0f);
    float fn = rintf(t);
    float f  = t - fn;
    float p  = 1.3333558e-3f;
    p = fmaf(p, f, 9.6181291e-3f);
    p = fmaf(p, f, 5.5504109e-2f);
    p = fmaf(p, f, 2.4022651e-1f);
    p = fmaf(p, f, 6.9314718e-1f);
    p = fmaf(p, f, 1.0f);
    int n = (int)fn;
    return p * __int_as_float((n + 127) << 23);
}

// ---------------- K-1: split fp32 -> packed bf16 hi/lo (transposed) ----------------
__global__ void k_split(const float* __restrict__ fin, const float* __restrict__ bin) {
    __shared__ float tile[32][33];
    int z = blockIdx.z;
    int isA = (z < BATCH);
    int b = isA ? z : z - BATCH;
    const float* src = (isA ? bin : fin) + (size_t)b * CH * PQ;
    __nv_bfloat16* dst = (isA ? g_Apack : g_Bpack) + (size_t)b * PQ * KTOT;

    int p0 = blockIdx.x * 32, c0 = blockIdx.y * 32;
    int tx = threadIdx.x, ty = threadIdx.y;   // (32, 8)
#pragma unroll
    for (int j = 0; j < 4; j++)
        tile[ty + 8 * j][tx] = src[(size_t)(c0 + ty + 8 * j) * PQ + p0 + tx];
    __syncthreads();
#pragma unroll
    for (int j = 0; j < 4; j++) {
        int r = ty + 8 * j;
        float a = tile[tx][r];
        __nv_bfloat16 hi = __float2bfloat16_rn(a);
        __nv_bfloat16 lo = __float2bfloat16_rn(a - __bfloat162float(hi));
        __nv_bfloat16* d = dst + (size_t)(p0 + r) * KTOT + c0 + tx;
        d[0]   = hi;
        d[128] = isA ? lo : hi;
        d[256] = isA ? hi : lo;
    }
}

// ---------------- K0a: ssq[b,p] = sum_c b[b,c,p]^2 ----------------
__global__ void k_ssq(const float* __restrict__ bin) {
    int p = blockIdx.x * 256 + threadIdx.x;
    int b = blockIdx.y;
    const float* src = bin + ((size_t)b * CH) * PQ + p;
    float s = 0.f;
#pragma unroll 8
    for (int c = 0; c < CH; c++) {
        float v = src[(size_t)c * PQ];
        s += v * v;
    }
    g_ssq[b * PQ + p] = s;
}

// ---------------- K0b: coef ----------------
__global__ void k_prep(const float* __restrict__ mask) {
    int p = blockIdx.x * 256 + threadIdx.x;
    int b = blockIdx.y;
    int py = p >> 6, px = p & 63;

    float s = EPS_SUM;
    bool masked = false;
#pragma unroll
    for (int dy = -1; dy <= 1; dy++) {
#pragma unroll
        for (int dx = -1; dx <= 1; dx++) {
            int yy = py + dy, xx = px + dx;
            if ((unsigned)yy < 64u && (unsigned)xx < 64u) {
                s += g_ssq[b * PQ + (yy << 6) + xx];
                if (mask[(size_t)(yy * 8) * 512 + xx * 8] != 0.0f) masked = true;
            }
        }
    }
    g_coef[b * PQ + p] = masked ? 0.0f : (SCALE * LOG2E / sqrtf(s));
    if (b == 0) g_mm[p] = masked ? 0.0f : 1.0f;
}

// ---------------- K1: HMMA bf16-split GEMM  Gt[p][q] = A.B ----------------
// CTA 128x128, K=384, BK=32, 256 thr = 8 warps (4 m x 2 n), warp tile 32x64.
// mma.sync m16n8k16 bf16 -> f32, cp.async double buffer.
__global__ __launch_bounds__(256, 2) void k_gemm_mma() {
    __shared__ __align__(16) __nv_bfloat16 sm[2][2][128][LDT];  // [stage][A/B][row][k]

    int tid = threadIdx.x;
    int wid = tid >> 5, lid = tid & 31;
    int g = lid >> 2, tig = lid & 3;
    int warp_m = wid & 3, warp_n = wid >> 2;

    int b  = blockIdx.z;
    int m0 = blockIdx.y * 128;   // p
    int n0 = blockIdx.x * 128;   // q
    const __nv_bfloat16* Ap = g_Apack + (size_t)b * PQ * KTOT;
    const __nv_bfloat16* Bp = g_Bpack + (size_t)b * PQ * KTOT;

    float acc[2][8][4];
#pragma unroll
    for (int mt = 0; mt < 2; mt++)
#pragma unroll
        for (int nt = 0; nt < 8; nt++)
#pragma unroll
            for (int i = 0; i < 4; i++) acc[mt][nt][i] = 0.f;

    // stage fill: 128 rows x 4 x 16B chunks per operand; 2+2 chunks/thread
    int frow = tid >> 2;
    int fcu  = (tid & 3) * 8;
    const __nv_bfloat16* gA = Ap + (size_t)(m0 + frow) * KTOT + fcu;
    const __nv_bfloat16* gB = Bp + (size_t)(n0 + frow) * KTOT + fcu;

    // prefetch stage 0
#pragma unroll
    for (int h = 0; h < 2; h++) {
        cpa16(&sm[0][0][frow + h * 64][fcu], gA + (size_t)(h * 64) * KTOT);
        cpa16(&sm[0][1][frow + h * 64][fcu], gB + (size_t)(h * 64) * KTOT);
    }
    CP_COMMIT();

#pragma unroll 1
    for (int kk = 0; kk < NKIT; kk++) {
        if (kk + 1 < NKIT) {
            int st = (kk + 1) & 1, ko = (kk + 1) * BKP;
#pragma unroll
            for (int h = 0; h < 2; h++) {
                cpa16(&sm[st][0][frow + h * 64][fcu], gA + (size_t)(h * 64) * KTOT + ko);
                cpa16(&sm[st][1][frow + h * 64][fcu], gB + (size_t)(h * 64) * KTOT + ko);
            }
            CP_COMMIT();
            CP_WAIT(1);
        } else {
            CP_WAIT(0);
        }
        __syncthreads();

        int buf = kk & 1;
#pragma unroll
        for (int ks = 0; ks < 2; ks++) {
            int kb = ks * 16 + tig * 2;
            uint32_t afr[2][4];
#pragma unroll
            for (int mt = 0; mt < 2; mt++) {
                int m = warp_m * 32 + mt * 16 + g;
                afr[mt][0] = *(const uint32_t*)&sm[buf][0][m][kb];
                afr[mt][1] = *(const uint32_t*)&sm[buf][0][m + 8][kb];
                afr[mt][2] = *(const uint32_t*)&sm[buf][0][m][kb + 8];
                afr[mt][3] = *(const uint32_t*)&sm[buf][0][m + 8][kb + 8];
            }
            uint32_t bfr[8][2];
#pragma unroll
            for (int nt = 0; nt < 8; nt++) {
                int n = warp_n * 64 + nt * 8 + g;
                bfr[nt][0] = *(const uint32_t*)&sm[buf][1][n][kb];
                bfr[nt][1] = *(const uint32_t*)&sm[buf][1][n][kb + 8];
            }
#pragma unroll
            for (int mt = 0; mt < 2; mt++)
#pragma unroll
                for (int nt = 0; nt < 8; nt++)
                    mma16816(acc[mt][nt], afr[mt], bfr[nt]);
        }
        __syncthreads();
    }

    // epilogue: each thread owns float2 pairs at (row g / g+8, col tig*2) per tile
    float* Gp = g_G + (size_t)b * PQ * PQ;
#pragma unroll
    for (int mt = 0; mt < 2; mt++) {
        int row = m0 + warp_m * 32 + mt * 16 + g;
#pragma unroll
        for (int nt = 0; nt < 8; nt++) {
            int col = n0 + warp_n * 64 + nt * 8 + tig * 2;
            *(float2*)&Gp[(size_t)row * PQ + col]       = make_float2(acc[mt][nt][0], acc[mt][nt][1]);
            *(float2*)&Gp[(size_t)(row + 8) * PQ + col] = make_float2(acc[mt][nt][2], acc[mt][nt][3]);
        }
    }
}

// ---------------- K2: 9-tap diagonal sum + exp2 + out + column partials ----------------
__global__ __launch_bounds__(256) void k_sum9(float* __restrict__ out) {
    int b    = blockIdx.z;
    int prow = blockIdx.y;
    int q    = blockIdx.x * 256 + threadIdx.x;
    int qy   = q >> 6, qx = q & 63;

    const float* __restrict__ Gp = g_G + (size_t)b * PQ * PQ;
    const float* __restrict__ cf = g_coef + b * PQ + prow * 64;

    const bool rvm = (prow > 0)  && (qy > 0);
    const bool rvp = (prow < 63) && (qy < 63);
    const bool qlf = (qx > 0), qrt = (qx < 63);

    const float* base = Gp + (size_t)(prow * 64) * PQ + q;
    float* orow = out + ((size_t)(b * PQ + prow * 64)) * PQ + q;
    float partial = 0.f;

#pragma unroll 4
    for (int px = 0; px < 64; px++) {
        bool lf = qlf && (px > 0);
        bool rt = qrt && (px < 63);
        float s = 0.f;
        if (rvm) {
            if (lf) s += __ldg(base - 65 * 4097);
            s += __ldg(base - 64 * 4097);
            if (rt) s += __ldg(base - 63 * 4097);
        }
        if (lf) s += __ldg(base - 4097);
        s += __ldg(base);
        if (rt) s += __ldg(base + 4097);
        if (rvp) {
            if (lf) s += __ldg(base + 63 * 4097);
            s += __ldg(base + 64 * 4097);
            if (rt) s += __ldg(base + 65 * 4097);
        }
        float e = fast_exp2(s * cf[px]);
        __stcs(orow, e);
        partial += e;
        base += PQ;
        orow += PQ;
    }
    g_partial[((size_t)(b * 64 + prow)) * PQ + q] = partial;
}

// ---------------- K2b: deterministic reduction of column partials ----------------
__global__ void k_colreduce() {
    int q = blockIdx.x * 256 + threadIdx.x;
    int b = blockIdx.y;
    const float* src = g_partial + (size_t)(b * 64) * PQ + q;
    float s = 0.f;
#pragma unroll 8
    for (int j = 0; j < 64; j++) s += src[(size_t)j * PQ];
    g_colsum[b * PQ + q] = s;
}

// ---------------- K3: normalize ----------------
__global__ void k_norm(float* __restrict__ out) {
    size_t i4  = (size_t)blockIdx.x * 256 + threadIdx.x;
    size_t row = i4 >> 10;
    int p  = (int)(row & 4095);
    int b  = (int)(row >> 12);
    int c4 = (int)(i4 & 1023);

    float4 v  = __ldcs((const float4*)out + i4);
    float  m  = g_mm[p];
    float4 cs = ((const float4*)g_colsum)[b * 1024 + c4];
    v.x = m * v.x / cs.x;
    v.y = m * v.y / cs.y;
    v.z = m * v.z / cs.z;
    v.w = m * v.w / cs.w;
    __stcs((float4*)out + i4, v);
}

// ---------------- launch ----------------
extern "C" void kernel_launch(void* const* d_in, const int* in_sizes, int n_in,
                              void* d_out, int out_size) {
    const float* f    = (const float*)d_in[0];
    const float* bb   = (const float*)d_in[1];
    const float* mask = (const float*)d_in[2];
    float* out = (float*)d_out;

    k_split    <<<dim3(PQ / 32, CH / 32, 2 * BATCH), dim3(32, 8)>>>(f, bb);
    k_ssq      <<<dim3(PQ / 256, BATCH), 256>>>(bb);
    k_prep     <<<dim3(PQ / 256, BATCH), 256>>>(mask);
    k_gemm_mma <<<dim3(PQ / 128, PQ / 128, BATCH), 256>>>();
    k_sum9     <<<dim3(PQ / 256, 64, BATCH), 256>>>(out);
    k_colreduce<<<dim3(PQ / 256, BATCH), 256>>>();
    k_norm     <<<(unsigned)(((size_t)BATCH * PQ * PQ / 4) / 256), 256>>>(out);
}

// round 10
// speedup vs baseline: 1.6138x; 1.0332x over previous
#include <cuda_runtime.h>
#include <cuda_bf16.h>
#include <cstdint>

// Problem constants
#define BATCH 4
#define CH    128
#define HW    64
#define PQ    4096            // HW*HW
#define SCALE 10.0f
#define EPS_SUM 0.1152f       // 128*3*3*1e-4
#define LOG2E 1.4426950408889634f
#define KTOT  384             // split-bf16 packed K (ah|al|ah vs bh|bh|bl)
#define BKP   32              // bf16 K per pipeline stage
#define NKIT  (KTOT / BKP)    // 12 stages
#define LDT   40              // padded smem row length (bf16)
#define STAGE_BYTES (2 * 128 * LDT * 2)   // one stage (A+B)  = 20480 B
#define BREG_OFF    (128 * LDT * 2)       // B region within a stage = 10240 B

// ---------------- static scratch ----------------
__device__ float g_G[(size_t)BATCH * PQ * PQ];   // Gt[b][p][q]  (256 MB)
__device__ float g_ssq[BATCH * PQ];
__device__ float g_coef[BATCH * PQ];
__device__ float g_mm[PQ];
__device__ float g_partial[BATCH * 64 * PQ];
__device__ float g_colsum[BATCH * PQ];
__device__ __nv_bfloat16 g_Apack[(size_t)BATCH * PQ * KTOT];  // from b: [p][ah|al|ah]
__device__ __nv_bfloat16 g_Bpack[(size_t)BATCH * PQ * KTOT];  // from f: [q][bh|bh|bl]

// ---------------- helpers ----------------
__device__ __forceinline__ uint32_t smem_u32(const void* p) {
    uint32_t a;
    asm("{ .reg .u64 t; cvta.to.shared.u64 t, %1; cvt.u32.u64 %0, t; }" : "=r"(a) : "l"(p));
    return a;
}
__device__ __forceinline__ void cpa16(void* dst, const void* src) {
    asm volatile("cp.async.ca.shared.global [%0], [%1], 16;"
                 :: "r"(smem_u32(dst)), "l"(src));
}
#define CP_COMMIT() asm volatile("cp.async.commit_group;" ::: "memory")
#define CP_WAIT(n)  asm volatile("cp.async.wait_group %0;" :: "n"(n) : "memory")

__device__ __forceinline__ void ldsm_x4(uint32_t* r, uint32_t addr) {
    asm volatile("ldmatrix.sync.aligned.m8n8.x4.shared.b16 {%0,%1,%2,%3}, [%4];"
                 : "=r"(r[0]), "=r"(r[1]), "=r"(r[2]), "=r"(r[3]) : "r"(addr));
}
__device__ __forceinline__ void mma16816(float* c, const uint32_t* a, const uint32_t* bfr) {
    asm volatile(
        "mma.sync.aligned.m16n8k16.row.col.f32.bf16.bf16.f32 "
        "{%0,%1,%2,%3}, {%4,%5,%6,%7}, {%8,%9}, {%0,%1,%2,%3};"
        : "+f"(c[0]), "+f"(c[1]), "+f"(c[2]), "+f"(c[3])
        : "r"(a[0]), "r"(a[1]), "r"(a[2]), "r"(a[3]), "r"(bfr[0]), "r"(bfr[1]));
}

// fast 2^t on the FMA pipe (degree-5, rel err ~2.4e-6)
__device__ __forceinline__ float fast_exp2(float t) {
    t = fminf(fmaxf(t, -120.0f), 120.0f);
    float fn = rintf(t);
    float f  = t - fn;
    float p  = 1.3333558e-3f;
    p = fmaf(p, f, 9.6181291e-3f);
    p = fmaf(p, f, 5.5504109e-2f);
    p = fmaf(p, f, 2.4022651e-1f);
    p = fmaf(p, f, 6.9314718e-1f);
    p = fmaf(p, f, 1.0f);
    int n = (int)fn;
    return p * __int_as_float((n + 127) << 23);
}

// ---------------- K-1: split fp32 -> packed bf16 hi/lo (transposed) ----------------
__global__ void k_split(const float* __restrict__ fin, const float* __restrict__ bin) {
    __shared__ float tile[32][33];
    int z = blockIdx.z;
    int isA = (z < BATCH);
    int b = isA ? z : z - BATCH;
    const float* src = (isA ? bin : fin) + (size_t)b * CH * PQ;
    __nv_bfloat16* dst = (isA ? g_Apack : g_Bpack) + (size_t)b * PQ * KTOT;

    int p0 = blockIdx.x * 32, c0 = blockIdx.y * 32;
    int tx = threadIdx.x, ty = threadIdx.y;   // (32, 8)
#pragma unroll
    for (int j = 0; j < 4; j++)
        tile[ty + 8 * j][tx] = src[(size_t)(c0 + ty + 8 * j) * PQ + p0 + tx];
    __syncthreads();
#pragma unroll
    for (int j = 0; j < 4; j++) {
        int r = ty + 8 * j;
        float a = tile[tx][r];
        __nv_bfloat16 hi = __float2bfloat16_rn(a);
        __nv_bfloat16 lo = __float2bfloat16_rn(a - __bfloat162float(hi));
        __nv_bfloat16* d = dst + (size_t)(p0 + r) * KTOT + c0 + tx;
        d[0]   = hi;
        d[128] = isA ? lo : hi;
        d[256] = isA ? hi : lo;
    }
}

// ---------------- K0a: ssq[b,p] = sum_c b[b,c,p]^2 ----------------
__global__ void k_ssq(const float* __restrict__ bin) {
    int p = blockIdx.x * 256 + threadIdx.x;
    int b = blockIdx.y;
    const float* src = bin + ((size_t)b * CH) * PQ + p;
    float s = 0.f;
#pragma unroll 8
    for (int c = 0; c < CH; c++) {
        float v = src[(size_t)c * PQ];
        s += v * v;
    }
    g_ssq[b * PQ + p] = s;
}

// ---------------- K0b: coef ----------------
__global__ void k_prep(const float* __restrict__ mask) {
    int p = blockIdx.x * 256 + threadIdx.x;
    int b = blockIdx.y;
    int py = p >> 6, px = p & 63;

    float s = EPS_SUM;
    bool masked = false;
#pragma unroll
    for (int dy = -1; dy <= 1; dy++) {
#pragma unroll
        for (int dx = -1; dx <= 1; dx++) {
            int yy = py + dy, xx = px + dx;
            if ((unsigned)yy < 64u && (unsigned)xx < 64u) {
                s += g_ssq[b * PQ + (yy << 6) + xx];
                if (mask[(size_t)(yy * 8) * 512 + xx * 8] != 0.0f) masked = true;
            }
        }
    }
    g_coef[b * PQ + p] = masked ? 0.0f : (SCALE * LOG2E / sqrtf(s));
    if (b == 0) g_mm[p] = masked ? 0.0f : 1.0f;
}

// ---------------- K1: HMMA bf16-split GEMM  Gt[p][q] = A.B (ldmatrix frags) --------
// CTA 128x128, K=384, BK=32, 256 thr = 8 warps (4 m x 2 n), warp tile 32x64.
__global__ __launch_bounds__(256, 2) void k_gemm_mma() {
    __shared__ __align__(16) __nv_bfloat16 sm[2][2][128][LDT];  // [stage][A/B][row][k]
    uint32_t sbase = smem_u32(&sm[0][0][0][0]);

    int tid = threadIdx.x;
    int wid = tid >> 5, lid = tid & 31;
    int g = lid >> 2, tig = lid & 3;
    int warp_m = wid & 3, warp_n = wid >> 2;

    int b  = blockIdx.z;
    int m0 = blockIdx.y * 128;   // p
    int n0 = blockIdx.x * 128;   // q
    const __nv_bfloat16* Ap = g_Apack + (size_t)b * PQ * KTOT;
    const __nv_bfloat16* Bp = g_Bpack + (size_t)b * PQ * KTOT;

    float acc[2][8][4];
#pragma unroll
    for (int mt = 0; mt < 2; mt++)
#pragma unroll
        for (int nt = 0; nt < 8; nt++)
#pragma unroll
            for (int i = 0; i < 4; i++) acc[mt][nt][i] = 0.f;

    // ldmatrix per-lane byte offsets within a stage
    // A x4: lanes 0-15 -> rows m+ (lid&15) @k0 ; lanes 16-31 -> same rows @k8
    uint32_t a_off[2];
#pragma unroll
    for (int mt = 0; mt < 2; mt++) {
        int row = warp_m * 32 + mt * 16 + (lid & 15);
        int kof = (lid >> 4) * 8;
        a_off[mt] = (uint32_t)((row * LDT + kof) * 2);
    }
    // B x4 (two n-tiles): lanes0-7 n0-7@k0, 8-15 n0-7@k8, 16-23 n8-15@k0, 24-31 n8-15@k8
    uint32_t b_off[4];
#pragma unroll
    for (int ntp = 0; ntp < 4; ntp++) {
        int row = warp_n * 64 + ntp * 16 + (lid & 7) + ((lid >> 4) << 3);
        int kof = ((lid >> 3) & 1) * 8;
        b_off[ntp] = (uint32_t)(BREG_OFF + (row * LDT + kof) * 2);
    }

    // stage fill: 128 rows x 4 x 16B chunks per operand; 2+2 chunks/thread
    int frow = tid >> 2;
    int fcu  = (tid & 3) * 8;
    const __nv_bfloat16* gA = Ap + (size_t)(m0 + frow) * KTOT + fcu;
    const __nv_bfloat16* gB = Bp + (size_t)(n0 + frow) * KTOT + fcu;

    // prefetch stage 0
#pragma unroll
    for (int h = 0; h < 2; h++) {
        cpa16(&sm[0][0][frow + h * 64][fcu], gA + (size_t)(h * 64) * KTOT);
        cpa16(&sm[0][1][frow + h * 64][fcu], gB + (size_t)(h * 64) * KTOT);
    }
    CP_COMMIT();

#pragma unroll 1
    for (int kk = 0; kk < NKIT; kk++) {
        if (kk + 1 < NKIT) {
            int st = (kk + 1) & 1, ko = (kk + 1) * BKP;
#pragma unroll
            for (int h = 0; h < 2; h++) {
                cpa16(&sm[st][0][frow + h * 64][fcu], gA + (size_t)(h * 64) * KTOT + ko);
                cpa16(&sm[st][1][frow + h * 64][fcu], gB + (size_t)(h * 64) * KTOT + ko);
            }
            CP_COMMIT();
            CP_WAIT(1);
        } else {
            CP_WAIT(0);
        }
        __syncthreads();

        uint32_t stg = sbase + (uint32_t)(kk & 1) * STAGE_BYTES;
#pragma unroll
        for (int ks = 0; ks < 2; ks++) {
            uint32_t kadj = (uint32_t)(ks * 32);   // 16 bf16 = 32 B
            uint32_t afr[2][4];
#pragma unroll
            for (int mt = 0; mt < 2; mt++) ldsm_x4(afr[mt], stg + a_off[mt] + kadj);
            uint32_t bfr[4][4];
#pragma unroll
            for (int ntp = 0; ntp < 4; ntp++) ldsm_x4(bfr[ntp], stg + b_off[ntp] + kadj);
#pragma unroll
            for (int mt = 0; mt < 2; mt++)
#pragma unroll
                for (int nt = 0; nt < 8; nt++)
                    mma16816(acc[mt][nt], afr[mt], &bfr[nt >> 1][(nt & 1) * 2]);
        }
        __syncthreads();
    }

    // epilogue: each thread owns float2 pairs at (row g / g+8, col tig*2) per tile
    float* Gp = g_G + (size_t)b * PQ * PQ;
#pragma unroll
    for (int mt = 0; mt < 2; mt++) {
        int row = m0 + warp_m * 32 + mt * 16 + g;
#pragma unroll
        for (int nt = 0; nt < 8; nt++) {
            int col = n0 + warp_n * 64 + nt * 8 + tig * 2;
            *(float2*)&Gp[(size_t)row * PQ + col]       = make_float2(acc[mt][nt][0], acc[mt][nt][1]);
            *(float2*)&Gp[(size_t)(row + 8) * PQ + col] = make_float2(acc[mt][nt][2], acc[mt][nt][3]);
        }
    }
}

// ---------------- K2: 9-tap diagonal sum + exp2 + out + column partials ----------------
__global__ __launch_bounds__(256) void k_sum9(float* __restrict__ out) {
    int b    = blockIdx.z;
    int prow = blockIdx.y;
    int q    = blockIdx.x * 256 + threadIdx.x;
    int qy   = q >> 6, qx = q & 63;

    const float* __restrict__ Gp = g_G + (size_t)b * PQ * PQ;
    const float* __restrict__ cf = g_coef + b * PQ + prow * 64;

    const bool rvm = (prow > 0)  && (qy > 0);
    const bool rvp = (prow < 63) && (qy < 63);
    const bool qlf = (qx > 0), qrt = (qx < 63);

    const float* base = Gp + (size_t)(prow * 64) * PQ + q;
    float* orow = out + ((size_t)(b * PQ + prow * 64)) * PQ + q;
    float partial = 0.f;

#pragma unroll 4
    for (int px = 0; px < 64; px++) {
        bool lf = qlf && (px > 0);
        bool rt = qrt && (px < 63);
        float s = 0.f;
        if (rvm) {
            if (lf) s += __ldg(base - 65 * 4097);
            s += __ldg(base - 64 * 4097);
            if (rt) s += __ldg(base - 63 * 4097);
        }
        if (lf) s += __ldg(base - 4097);
        s += __ldg(base);
        if (rt) s += __ldg(base + 4097);
        if (rvp) {
            if (lf) s += __ldg(base + 63 * 4097);
            s += __ldg(base + 64 * 4097);
            if (rt) s += __ldg(base + 65 * 4097);
        }
        float e = fast_exp2(s * cf[px]);
        __stcs(orow, e);
        partial += e;
        base += PQ;
        orow += PQ;
    }
    g_partial[((size_t)(b * 64 + prow)) * PQ + q] = partial;
}

// ---------------- K2b: deterministic reduction of column partials ----------------
__global__ void k_colreduce() {
    int q = blockIdx.x * 256 + threadIdx.x;
    int b = blockIdx.y;
    const float* src = g_partial + (size_t)(b * 64) * PQ + q;
    float s = 0.f;
#pragma unroll 8
    for (int j = 0; j < 64; j++) s += src[(size_t)j * PQ];
    g_colsum[b * PQ + q] = s;
}

// ---------------- K3: normalize ----------------
__global__ void k_norm(float* __restrict__ out) {
    size_t i4  = (size_t)blockIdx.x * 256 + threadIdx.x;
    size_t row = i4 >> 10;
    int p  = (int)(row & 4095);
    int b  = (int)(row >> 12);
    int c4 = (int)(i4 & 1023);

    float4 v  = __ldcs((const float4*)out + i4);
    float  m  = g_mm[p];
    float4 cs = ((const float4*)g_colsum)[b * 1024 + c4];
    v.x = m * v.x / cs.x;
    v.y = m * v.y / cs.y;
    v.z = m * v.z / cs.z;
    v.w = m * v.w / cs.w;
    __stcs((float4*)out + i4, v);
}

// ---------------- launch ----------------
extern "C" void kernel_launch(void* const* d_in, const int* in_sizes, int n_in,
                              void* d_out, int out_size) {
    const float* f    = (const float*)d_in[0];
    const float* bb   = (const float*)d_in[1];
    const float* mask = (const float*)d_in[2];
    float* out = (float*)d_out;

    k_split    <<<dim3(PQ / 32, CH / 32, 2 * BATCH), dim3(32, 8)>>>(f, bb);
    k_ssq      <<<dim3(PQ / 256, BATCH), 256>>>(bb);
    k_prep     <<<dim3(PQ / 256, BATCH), 256>>>(mask);
    k_gemm_mma <<<dim3(PQ / 128, PQ / 128, BATCH), 256>>>();
    k_sum9     <<<dim3(PQ / 256, 64, BATCH), 256>>>(out);
    k_colreduce<<<dim3(PQ / 256, BATCH), 256>>>();
    k_norm     <<<(unsigned)(((size_t)BATCH * PQ * PQ / 4) / 256), 256>>>(out);
}

// round 11
// speedup vs baseline: 1.6374x; 1.0146x over previous
#include <cuda_runtime.h>
#include <cuda_bf16.h>
#include <cstdint>

// Problem constants
#define BATCH 4
#define CH    128
#define HW    64
#define PQ    4096            // HW*HW
#define SCALE 10.0f
#define EPS_SUM 0.1152f       // 128*3*3*1e-4
#define LOG2E 1.4426950408889634f
#define KTOT  384             // split-bf16 packed K (ah|al|ah vs bh|bh|bl)
#define BKP   32              // bf16 K per pipeline stage
#define NKIT  (KTOT / BKP)    // 12 stages
#define LDT   40              // padded smem row length (bf16)
#define STAGE_BYTES (2 * 128 * LDT * 2)   // one stage (A+B)  = 20480 B
#define BREG_OFF    (128 * LDT * 2)       // B region within a stage = 10240 B

// ---------------- static scratch ----------------
__device__ float g_G[(size_t)BATCH * PQ * PQ];   // Gt[b][p][q]  (256 MB)
__device__ float g_ssq[BATCH * PQ];
__device__ float g_coef[BATCH * PQ];
__device__ float g_mm[PQ];
__device__ float g_partial[BATCH * 64 * PQ];
__device__ float g_colsum[BATCH * PQ];
__device__ __nv_bfloat16 g_Apack[(size_t)BATCH * PQ * KTOT];  // from b: [p][ah|al|ah]
__device__ __nv_bfloat16 g_Bpack[(size_t)BATCH * PQ * KTOT];  // from f: [q][bh|bh|bl]

// ---------------- helpers ----------------
__device__ __forceinline__ uint32_t smem_u32(const void* p) {
    uint32_t a;
    asm("{ .reg .u64 t; cvta.to.shared.u64 t, %1; cvt.u32.u64 %0, t; }" : "=r"(a) : "l"(p));
    return a;
}
__device__ __forceinline__ void cpa16(void* dst, const void* src) {
    asm volatile("cp.async.ca.shared.global [%0], [%1], 16;"
                 :: "r"(smem_u32(dst)), "l"(src));
}
#define CP_COMMIT() asm volatile("cp.async.commit_group;" ::: "memory")
#define CP_WAIT(n)  asm volatile("cp.async.wait_group %0;" :: "n"(n) : "memory")

__device__ __forceinline__ void ldsm_x4(uint32_t* r, uint32_t addr) {
    asm volatile("ldmatrix.sync.aligned.m8n8.x4.shared.b16 {%0,%1,%2,%3}, [%4];"
                 : "=r"(r[0]), "=r"(r[1]), "=r"(r[2]), "=r"(r[3]) : "r"(addr));
}
__device__ __forceinline__ void mma16816(float* c, const uint32_t* a, const uint32_t* bfr) {
    asm volatile(
        "mma.sync.aligned.m16n8k16.row.col.f32.bf16.bf16.f32 "
        "{%0,%1,%2,%3}, {%4,%5,%6,%7}, {%8,%9}, {%0,%1,%2,%3};"
        : "+f"(c[0]), "+f"(c[1]), "+f"(c[2]), "+f"(c[3])
        : "r"(a[0]), "r"(a[1]), "r"(a[2]), "r"(a[3]), "r"(bfr[0]), "r"(bfr[1]));
}

// fast 2^t on the FMA pipe (degree-5, rel err ~2.4e-6)
__device__ __forceinline__ float fast_exp2(float t) {
    t = fminf(fmaxf(t, -120.0f), 120.0f);
    float fn = rintf(t);
    float f  = t - fn;
    float p  = 1.3333558e-3f;
    p = fmaf(p, f, 9.6181291e-3f);
    p = fmaf(p, f, 5.5504109e-2f);
    p = fmaf(p, f, 2.4022651e-1f);
    p = fmaf(p, f, 6.9314718e-1f);
    p = fmaf(p, f, 1.0f);
    int n = (int)fn;
    return p * __int_as_float((n + 127) << 23);
}

// ---------------- K-1: split fp32 -> packed bf16 hi/lo (transposed) ----------------
__global__ void k_split(const float* __restrict__ fin, const float* __restrict__ bin) {
    __shared__ float tile[32][33];
    int z = blockIdx.z;
    int isA = (z < BATCH);
    int b = isA ? z : z - BATCH;
    const float* src = (isA ? bin : fin) + (size_t)b * CH * PQ;
    __nv_bfloat16* dst = (isA ? g_Apack : g_Bpack) + (size_t)b * PQ * KTOT;

    int p0 = blockIdx.x * 32, c0 = blockIdx.y * 32;
    int tx = threadIdx.x, ty = threadIdx.y;   // (32, 8)
#pragma unroll
    for (int j = 0; j < 4; j++)
        tile[ty + 8 * j][tx] = src[(size_t)(c0 + ty + 8 * j) * PQ + p0 + tx];
    __syncthreads();
#pragma unroll
    for (int j = 0; j < 4; j++) {
        int r = ty + 8 * j;
        float a = tile[tx][r];
        __nv_bfloat16 hi = __float2bfloat16_rn(a);
        __nv_bfloat16 lo = __float2bfloat16_rn(a - __bfloat162float(hi));
        __nv_bfloat16* d = dst + (size_t)(p0 + r) * KTOT + c0 + tx;
        d[0]   = hi;
        d[128] = isA ? lo : hi;
        d[256] = isA ? hi : lo;
    }
}

// ---------------- K0a: ssq[b,p] = sum_c b[b,c,p]^2 ----------------
__global__ void k_ssq(const float* __restrict__ bin) {
    int p = blockIdx.x * 256 + threadIdx.x;
    int b = blockIdx.y;
    const float* src = bin + ((size_t)b * CH) * PQ + p;
    float s = 0.f;
#pragma unroll 8
    for (int c = 0; c < CH; c++) {
        float v = src[(size_t)c * PQ];
        s += v * v;
    }
    g_ssq[b * PQ + p] = s;
}

// ---------------- K0b: coef ----------------
__global__ void k_prep(const float* __restrict__ mask) {
    int p = blockIdx.x * 256 + threadIdx.x;
    int b = blockIdx.y;
    int py = p >> 6, px = p & 63;

    float s = EPS_SUM;
    bool masked = false;
#pragma unroll
    for (int dy = -1; dy <= 1; dy++) {
#pragma unroll
        for (int dx = -1; dx <= 1; dx++) {
            int yy = py + dy, xx = px + dx;
            if ((unsigned)yy < 64u && (unsigned)xx < 64u) {
                s += g_ssq[b * PQ + (yy << 6) + xx];
                if (mask[(size_t)(yy * 8) * 512 + xx * 8] != 0.0f) masked = true;
            }
        }
    }
    g_coef[b * PQ + p] = masked ? 0.0f : (SCALE * LOG2E / sqrtf(s));
    if (b == 0) g_mm[p] = masked ? 0.0f : 1.0f;
}

// ---------------- K1: HMMA bf16-split GEMM  Gt[p][q] = A.B (64x64 warp tile) -------
// CTA 128x128, K=384, BK=32, 128 thr = 4 warps (2 m x 2 n), warp tile 64x64.
__global__ __launch_bounds__(128, 2) void k_gemm_mma() {
    __shared__ __align__(16) __nv_bfloat16 sm[2][2][128][LDT];  // [stage][A/B][row][k]
    uint32_t sbase = smem_u32(&sm[0][0][0][0]);

    int tid = threadIdx.x;
    int wid = tid >> 5, lid = tid & 31;
    int g = lid >> 2, tig = lid & 3;
    int warp_m = wid & 1, warp_n = wid >> 1;

    int b  = blockIdx.z;
    int m0 = blockIdx.y * 128;   // p
    int n0 = blockIdx.x * 128;   // q
    const __nv_bfloat16* Ap = g_Apack + (size_t)b * PQ * KTOT;
    const __nv_bfloat16* Bp = g_Bpack + (size_t)b * PQ * KTOT;

    float acc[4][8][4];
#pragma unroll
    for (int mt = 0; mt < 4; mt++)
#pragma unroll
        for (int nt = 0; nt < 8; nt++)
#pragma unroll
            for (int i = 0; i < 4; i++) acc[mt][nt][i] = 0.f;

    // ldmatrix per-lane byte offsets within a stage
    // A x4: lanes 0-15 -> rows m + (lid&15) @k0 ; lanes 16-31 -> same rows @k8
    uint32_t a_off[4];
#pragma unroll
    for (int mt = 0; mt < 4; mt++) {
        int row = warp_m * 64 + mt * 16 + (lid & 15);
        int kof = (lid >> 4) * 8;
        a_off[mt] = (uint32_t)((row * LDT + kof) * 2);
    }
    // B x4 (two n-tiles): lanes0-7 n0-7@k0, 8-15 n0-7@k8, 16-23 n8-15@k0, 24-31 n8-15@k8
    uint32_t b_off[4];
#pragma unroll
    for (int ntp = 0; ntp < 4; ntp++) {
        int row = warp_n * 64 + ntp * 16 + (lid & 7) + ((lid >> 4) << 3);
        int kof = ((lid >> 3) & 1) * 8;
        b_off[ntp] = (uint32_t)(BREG_OFF + (row * LDT + kof) * 2);
    }

    // stage fill: 128 rows x 4 x 16B chunks per operand; 4+4 chunks/thread (128 thr)
    int frow = tid >> 2;            // 0..31
    int fcu  = (tid & 3) * 8;
    const __nv_bfloat16* gA = Ap + (size_t)(m0 + frow) * KTOT + fcu;
    const __nv_bfloat16* gB = Bp + (size_t)(n0 + frow) * KTOT + fcu;

    // prefetch stage 0
#pragma unroll
    for (int h = 0; h < 4; h++) {
        cpa16(&sm[0][0][frow + h * 32][fcu], gA + (size_t)(h * 32) * KTOT);
        cpa16(&sm[0][1][frow + h * 32][fcu], gB + (size_t)(h * 32) * KTOT);
    }
    CP_COMMIT();

#pragma unroll 1
    for (int kk = 0; kk < NKIT; kk++) {
        if (kk + 1 < NKIT) {
            int st = (kk + 1) & 1, ko = (kk + 1) * BKP;
#pragma unroll
            for (int h = 0; h < 4; h++) {
                cpa16(&sm[st][0][frow + h * 32][fcu], gA + (size_t)(h * 32) * KTOT + ko);
                cpa16(&sm[st][1][frow + h * 32][fcu], gB + (size_t)(h * 32) * KTOT + ko);
            }
            CP_COMMIT();
            CP_WAIT(1);
        } else {
            CP_WAIT(0);
        }
        __syncthreads();

        uint32_t stg = sbase + (uint32_t)(kk & 1) * STAGE_BYTES;
#pragma unroll
        for (int ks = 0; ks < 2; ks++) {
            uint32_t kadj = (uint32_t)(ks * 32);   // 16 bf16 = 32 B
            uint32_t afr[4][4];
#pragma unroll
            for (int mt = 0; mt < 4; mt++) ldsm_x4(afr[mt], stg + a_off[mt] + kadj);
            uint32_t bfr[4][4];
#pragma unroll
            for (int ntp = 0; ntp < 4; ntp++) ldsm_x4(bfr[ntp], stg + b_off[ntp] + kadj);
#pragma unroll
            for (int mt = 0; mt < 4; mt++)
#pragma unroll
                for (int nt = 0; nt < 8; nt++)
                    mma16816(acc[mt][nt], afr[mt], &bfr[nt >> 1][(nt & 1) * 2]);
        }
        __syncthreads();
    }

    // epilogue: each thread owns float2 pairs at (row g / g+8, col tig*2) per tile
    float* Gp = g_G + (size_t)b * PQ * PQ;
#pragma unroll
    for (int mt = 0; mt < 4; mt++) {
        int row = m0 + warp_m * 64 + mt * 16 + g;
#pragma unroll
        for (int nt = 0; nt < 8; nt++) {
            int col = n0 + warp_n * 64 + nt * 8 + tig * 2;
            *(float2*)&Gp[(size_t)row * PQ + col]       = make_float2(acc[mt][nt][0], acc[mt][nt][1]);
            *(float2*)&Gp[(size_t)(row + 8) * PQ + col] = make_float2(acc[mt][nt][2], acc[mt][nt][3]);
        }
    }
}

// ---------------- K2: 9-tap diagonal sum + exp2 + out + column partials ----------------
__global__ __launch_bounds__(256) void k_sum9(float* __restrict__ out) {
    int b    = blockIdx.z;
    int prow = blockIdx.y;
    int q    = blockIdx.x * 256 + threadIdx.x;
    int qy   = q >> 6, qx = q & 63;

    const float* __restrict__ Gp = g_G + (size_t)b * PQ * PQ;
    const float* __restrict__ cf = g_coef + b * PQ + prow * 64;

    const bool rvm = (prow > 0)  && (qy > 0);
    const bool rvp = (prow < 63) && (qy < 63);
    const bool qlf = (qx > 0), qrt = (qx < 63);

    const float* base = Gp + (size_t)(prow * 64) * PQ + q;
    float* orow = out + ((size_t)(b * PQ + prow * 64)) * PQ + q;
    float partial = 0.f;

#pragma unroll 8
    for (int px = 0; px < 64; px++) {
        bool lf = qlf && (px > 0);
        bool rt = qrt && (px < 63);
        float s = 0.f;
        if (rvm) {
            if (lf) s += __ldg(base - 65 * 4097);
            s += __ldg(base - 64 * 4097);
            if (rt) s += __ldg(base - 63 * 4097);
        }
        if (lf) s += __ldg(base - 4097);
        s += __ldg(base);
        if (rt) s += __ldg(base + 4097);
        if (rvp) {
            if (lf) s += __ldg(base + 63 * 4097);
            s += __ldg(base + 64 * 4097);
            if (rt) s += __ldg(base + 65 * 4097);
        }
        float e = fast_exp2(s * cf[px]);
        __stcs(orow, e);
        partial += e;
        base += PQ;
        orow += PQ;
    }
    g_partial[((size_t)(b * 64 + prow)) * PQ + q] = partial;
}

// ---------------- K2b: deterministic reduction of column partials ----------------
__global__ void k_colreduce() {
    int q = blockIdx.x * 256 + threadIdx.x;
    int b = blockIdx.y;
    const float* src = g_partial + (size_t)(b * 64) * PQ + q;
    float s = 0.f;
#pragma unroll 8
    for (int j = 0; j < 64; j++) s += src[(size_t)j * PQ];
    g_colsum[b * PQ + q] = s;
}

// ---------------- K3: normalize ----------------
__global__ void k_norm(float* __restrict__ out) {
    size_t i4  = (size_t)blockIdx.x * 256 + threadIdx.x;
    size_t row = i4 >> 10;
    int p  = (int)(row & 4095);
    int b  = (int)(row >> 12);
    int c4 = (int)(i4 & 1023);

    float4 v  = __ldcs((const float4*)out + i4);
    float  m  = g_mm[p];
    float4 cs = ((const float4*)g_colsum)[b * 1024 + c4];
    v.x = m * v.x / cs.x;
    v.y = m * v.y / cs.y;
    v.z = m * v.z / cs.z;
    v.w = m * v.w / cs.w;
    __stcs((float4*)out + i4, v);
}

// ---------------- launch ----------------
extern "C" void kernel_launch(void* const* d_in, const int* in_sizes, int n_in,
                              void* d_out, int out_size) {
    const float* f    = (const float*)d_in[0];
    const float* bb   = (const float*)d_in[1];
    const float* mask = (const float*)d_in[2];
    float* out = (float*)d_out;

    k_split    <<<dim3(PQ / 32, CH / 32, 2 * BATCH), dim3(32, 8)>>>(f, bb);
    k_ssq      <<<dim3(PQ / 256, BATCH), 256>>>(bb);
    k_prep     <<<dim3(PQ / 256, BATCH), 256>>>(mask);
    k_gemm_mma <<<dim3(PQ / 128, PQ / 128, BATCH), 128>>>();
    k_sum9     <<<dim3(PQ / 256, 64, BATCH), 256>>>(out);
    k_colreduce<<<dim3(PQ / 256, BATCH), 256>>>();
    k_norm     <<<(unsigned)(((size_t)BATCH * PQ * PQ / 4) / 256), 256>>>(out);
}